// round 6
// baseline (speedup 1.0000x reference)
#include <cuda_runtime.h>

// ============================================================================
// Layer_70411693850653 — equivariant GNN layer, fully fused.
//
//  * messages[384:640] never consumed -> skipped
//  * agg == 1.5 * feats[:, :128] -> skip connection folded into weights
//  * scatter_mean via bucketed inverse-CSR + register gather (no float atomics)
//  * bucket stores {sender, edge} -> no random senders[] gather in hot loop
//  * weights precomputed to GLOBAL (L1-resident) in k_fill's extra blocks:
//    smem = sF only (24KB) -> 5 blocks/SM at TILE=16 (8 rows/warp, 36 L1
//    ops/row vs 48 at TILE=8)
//  * Phase B: scalar FFMA + float4 smem loads (measured-best form)
// ============================================================================

#define N_MAX 50000
#define CAP   32
#define TILE  16
#define FS    384
#define NBLK  740         // 5 per SM on 148 SMs

__device__ int   g_deg[N_MAX];            // zero-init at load; k_main resets
__device__ int2  g_bucket[N_MAX * CAP];   // {sender, edge}
__device__ float g_W0e[96 * 32];          // effective weights (skip folded)
__device__ float g_W1e[96 * 32];

// ---------------------------------------------------------------------------
// Blocks [0, EB): bucket fill.  Blocks [EB, EB+6): weight prep.
__global__ void k_fill(const int* __restrict__ recv,
                       const int* __restrict__ senders, int E, int EB,
                       const float* __restrict__ W0, const float* __restrict__ W1,
                       const float* __restrict__ Ws0, const float* __restrict__ Ws1)
{
    if ((int)blockIdx.x < EB) {
        int e = blockIdx.x * 512 + threadIdx.x;
        if (e < E) {
            int r = recv[e];
            int slot = atomicAdd(&g_deg[r], 1);
            if (slot < CAP) g_bucket[r * CAP + slot] = make_int2(senders[e], e);
        }
    } else {
        const float invA = 0.10206207261596575f;         // 1/sqrt(96)
        const float cB   = 1.5f * 0.17677669529663687f;  // 1.5/sqrt(32)
        int i = (blockIdx.x - EB) * 512 + threadIdx.x;
        if (i < 96 * 32) {
            int u = i >> 5;
            float w0 = W0[i] * invA;
            float w1 = W1[i] * invA;
            if (u < 32) { w0 = fmaf(cB, Ws0[i], w0); w1 = fmaf(cB, Ws1[i], w1); }
            g_W0e[i] = w0;
            g_W1e[i] = w1;
        }
    }
}

// ---------------------------------------------------------------------------
__global__ void __launch_bounds__(256, 5) k_main(
    const float* __restrict__ nf, const float* __restrict__ sh,
    float* __restrict__ out, int N)
{
    __shared__ __align__(16) float sF[TILE * FS];

    const float INV_SQRT3 = 0.5773502691896258f;

    const int t    = threadIdx.x;
    const int w    = t >> 5;
    const int lane = t & 31;

    const int ntiles = (N + TILE - 1) / TILE;
    for (int tile = blockIdx.x; tile < ntiles; tile += gridDim.x) {
        __syncthreads();   // protect sF against previous iteration's readers

        // ---------------- Phase A: 2 nodes per warp ------------------------
        #pragma unroll
        for (int half = 0; half < 2; half++) {
            const int ni = half * 8 + w;
            const int n  = tile * TILE + ni;

            float a0 = 0.f, ax = 0.f, ay = 0.f, az = 0.f;
            float p00 = 0.f, dot = 0.f;
            float qx = 0.f, qy = 0.f, qz = 0.f;   // p01 = s0*f1
            float rx = 0.f, ry = 0.f, rz = 0.f;   // p10 = f0*s1

            int d = 0;
            if (n < N) d = g_deg[n];
            const int dc = min(d, CAP);
            if (n < N && lane == 0) g_deg[n] = 0;   // maintain zero-invariant

            int    my_s  = 0;
            float4 my_sh = make_float4(0.f, 0.f, 0.f, 0.f);
            if (lane < dc) {
                int2 se = g_bucket[n * CAP + lane];
                my_s    = se.x;
                my_sh   = *reinterpret_cast<const float4*>(sh + (size_t)se.y * 4);
            }

            for (int j = 0; j < dc; j++) {
                int   s   = __shfl_sync(0xffffffffu, my_s,    j);
                float s0  = __shfl_sync(0xffffffffu, my_sh.x, j);
                float s1x = __shfl_sync(0xffffffffu, my_sh.y, j);
                float s1y = __shfl_sync(0xffffffffu, my_sh.z, j);
                float s1z = __shfl_sync(0xffffffffu, my_sh.w, j);

                const float* row = nf + (size_t)s * 128;
                float f0 = row[lane];
                float g0 = row[32 + 3 * lane];
                float g1 = row[33 + 3 * lane];
                float g2 = row[34 + 3 * lane];

                a0 += f0; ax += g0; ay += g1; az += g2;
                p00 = fmaf(s0, f0, p00);
                dot = fmaf(s1x, g0, fmaf(s1y, g1, fmaf(s1z, g2, dot)));
                qx  = fmaf(s0, g0, qx);
                qy  = fmaf(s0, g1, qy);
                qz  = fmaf(s0, g2, qz);
                rx  = fmaf(f0, s1x, rx);
                ry  = fmaf(f0, s1y, ry);
                rz  = fmaf(f0, s1z, rz);
            }

            const float scale = 1.0f / (1.5f * (float)max(d, 1));
            float* F = sF + ni * FS;
            F[        lane] = a0 * scale;
            F[ 32   + lane] = ax * scale;
            F[ 64   + lane] = ay * scale;
            F[ 96   + lane] = az * scale;
            F[128   + lane] = p00 * scale;
            F[160   + lane] = dot * scale * INV_SQRT3;
            F[192   + lane] = qx * scale;   // c=0: p01
            F[224   + lane] = rx * scale;   // c=0: p10
            F[256   + lane] = qy * scale;   // c=1
            F[288   + lane] = ry * scale;
            F[320   + lane] = qz * scale;   // c=2
            F[352   + lane] = rz * scale;
        }
        __syncthreads();

        // ---------------- Phase B: 64 rows (16 nodes x 4) / 8 warps --------
        // warp 0,1 : scalar channel, nodes 0-7 / 8-15, weights g_W0e
        // warp 2-7 : vector comp c=(w-2)>>1, nodes ((w-2)&1)*8.., g_W1e
        const float* Wc;
        int nodeBase, cc;
        if (w < 2) { Wc = g_W0e; nodeBase = w * 8; cc = -1; }
        else       { cc = (w - 2) >> 1; nodeBase = ((w - 2) & 1) * 8; Wc = g_W1e; }

        const float* pA = (cc < 0) ? (sF + nodeBase * FS)
                                   : (sF + nodeBase * FS + 32 + 32 * cc);
        const float* pB = (cc < 0) ? (sF + nodeBase * FS + 128)
                                   : (sF + nodeBase * FS + 192 + 64 * cc);

        float acc[8];
        #pragma unroll
        for (int r = 0; r < 8; r++) acc[r] = 0.f;

        #pragma unroll
        for (int u = 0; u < 32; u += 4) {
            float wv0 = __ldg(Wc + (u + 0) * 32 + lane);
            float wv1 = __ldg(Wc + (u + 1) * 32 + lane);
            float wv2 = __ldg(Wc + (u + 2) * 32 + lane);
            float wv3 = __ldg(Wc + (u + 3) * 32 + lane);
            #pragma unroll
            for (int r = 0; r < 8; r++) {
                float4 a = *reinterpret_cast<const float4*>(pA + r * FS + u);
                acc[r] = fmaf(a.x, wv0, fmaf(a.y, wv1,
                         fmaf(a.z, wv2, fmaf(a.w, wv3, acc[r]))));
            }
        }
        #pragma unroll
        for (int u = 0; u < 64; u += 4) {
            float wv0 = __ldg(Wc + (32 + u) * 32 + lane);
            float wv1 = __ldg(Wc + (33 + u) * 32 + lane);
            float wv2 = __ldg(Wc + (34 + u) * 32 + lane);
            float wv3 = __ldg(Wc + (35 + u) * 32 + lane);
            #pragma unroll
            for (int r = 0; r < 8; r++) {
                float4 a = *reinterpret_cast<const float4*>(pB + r * FS + u);
                acc[r] = fmaf(a.x, wv0, fmaf(a.y, wv1,
                         fmaf(a.z, wv2, fmaf(a.w, wv3, acc[r]))));
            }
        }

        #pragma unroll
        for (int r = 0; r < 8; r++) {
            int n = tile * TILE + nodeBase + r;
            if (n < N) {
                if (cc < 0) out[(size_t)n * 128 + lane] = acc[r];
                else        out[(size_t)n * 128 + 32 + 3 * lane + cc] = acc[r];
            }
        }
    }
}

// ---------------------------------------------------------------------------
extern "C" void kernel_launch(void* const* d_in, const int* in_sizes, int n_in,
                              void* d_out, int out_size)
{
    const float* nf       = (const float*)d_in[0];
    const float* sh       = (const float*)d_in[1];
    const int*   senders  = (const int*)  d_in[2];
    const int*   recv     = (const int*)  d_in[3];
    const float* W0       = (const float*)d_in[4];
    const float* W1       = (const float*)d_in[5];
    const float* Ws0      = (const float*)d_in[6];
    const float* Ws1      = (const float*)d_in[7];
    float* out = (float*)d_out;

    int N = in_sizes[0] / 128;
    int E = in_sizes[2];

    int EB = (E + 511) / 512;               // edge blocks
    int WB = (96 * 32 + 511) / 512;         // weight-prep blocks (6)
    k_fill<<<EB + WB, 512>>>(recv, senders, E, EB, W0, W1, Ws0, Ws1);
    k_main<<<NBLK, 256>>>(nf, sh, out, N);
}

// round 7
// speedup vs baseline: 1.1705x; 1.1705x over previous
#include <cuda_runtime.h>

// ============================================================================
// Layer_70411693850653 — equivariant GNN layer, fully fused. (R5 base)
//
//  * messages[384:640] never consumed -> skipped
//  * agg == 1.5 * feats[:, :128] -> skip connection folded into weights
//  * scatter_mean via bucketed inverse-CSR + register gather (no float atomics)
//  * bucket stores {sender, edge} -> no random senders[] gather in hot loop
//  * NEW(R7): g_nfT interleaved {f0,g0,g1,g2} table (built in k_fill's extra
//    blocks) -> Phase A = ONE coalesced LDG.128/edge instead of 4 strided LDG
//  * NEW(R7): smem weights packed as float4 u-quads -> 24 instead of 96
//    weight-load instructions per warp-tile
//  * TILE=8, 36KB smem, 6 blocks/SM; Phase B scalar FFMA (measured-best form)
// ============================================================================

#define N_MAX 50000
#define CAP   32
#define TILE  8
#define FS    384
#define NBLK  888         // 6 per SM on 148 SMs

__device__ int    g_deg[N_MAX];            // zero-init at load; k_main resets
__device__ int2   g_bucket[N_MAX * CAP];   // {sender, edge}
__device__ float4 g_nfT[N_MAX * 32];       // [n][lane] = {f0, g0, g1, g2}

// ---------------------------------------------------------------------------
// Blocks [0,EB): bucket fill.  [EB, EB+TB): nf transpose (16 warps = 16 nodes).
__global__ void __launch_bounds__(512) k_fill(
    const int* __restrict__ recv, const int* __restrict__ senders,
    const float* __restrict__ nf, int E, int EB, int N)
{
    if ((int)blockIdx.x < EB) {
        int e = blockIdx.x * 512 + threadIdx.x;
        if (e < E) {
            int r = recv[e];
            int slot = atomicAdd(&g_deg[r], 1);
            if (slot < CAP) g_bucket[r * CAP + slot] = make_int2(senders[e], e);
        }
    } else {
        __shared__ float tbuf[16][128];
        const int wid = threadIdx.x >> 5, lane = threadIdx.x & 31;
        const int n = ((int)blockIdx.x - EB) * 16 + wid;
        if (n < N) {
            reinterpret_cast<float4*>(tbuf[wid])[lane] =
                reinterpret_cast<const float4*>(nf + (size_t)n * 128)[lane];
            __syncwarp();
            float4 v;
            v.x = tbuf[wid][lane];                 // f0
            v.y = tbuf[wid][32 + 3 * lane];        // g0   (stride-3: no conflicts)
            v.z = tbuf[wid][33 + 3 * lane];        // g1
            v.w = tbuf[wid][34 + 3 * lane];        // g2
            g_nfT[n * 32 + lane] = v;
        }
    }
}

// ---------------------------------------------------------------------------
__global__ void __launch_bounds__(256, 6) k_main(
    const float* __restrict__ sh,
    const float* __restrict__ W0, const float* __restrict__ W1,
    const float* __restrict__ Ws0, const float* __restrict__ Ws1,
    float* __restrict__ out, int N)
{
    // weights as u-quads: sWq[q*32 + lane] = {W[4q][lane], .., W[4q+3][lane]}
    __shared__ __align__(16) float4 sW0q[24 * 32];
    __shared__ __align__(16) float4 sW1q[24 * 32];
    __shared__ __align__(16) float  sF[TILE * FS];

    const float invA = 0.10206207261596575f;         // 1/sqrt(96)
    const float cB   = 1.5f * 0.17677669529663687f;  // 1.5/sqrt(32)
    const float INV_SQRT3 = 0.5773502691896258f;

    const int t    = threadIdx.x;
    const int w    = t >> 5;
    const int lane = t & 31;

    // Effective weights (skip folded), packed into quads
    for (int i = t; i < 24 * 32; i += 256) {
        int q = i >> 5, l = i & 31;
        float4 a, b;
        float* pa = &a.x; float* pb = &b.x;
        #pragma unroll
        for (int k = 0; k < 4; k++) {
            int u = 4 * q + k;
            float w0 = W0[u * 32 + l] * invA;
            float w1 = W1[u * 32 + l] * invA;
            if (u < 32) { w0 = fmaf(cB, Ws0[u * 32 + l], w0);
                          w1 = fmaf(cB, Ws1[u * 32 + l], w1); }
            pa[k] = w0; pb[k] = w1;
        }
        sW0q[i] = a;
        sW1q[i] = b;
    }

    const int ntiles = (N + TILE - 1) / TILE;
    for (int tile = blockIdx.x; tile < ntiles; tile += gridDim.x) {
        __syncthreads();   // protect sF against previous iteration's readers

        // ---------------- Phase A: warp w owns node tile*8 + w -------------
        {
            const int n = tile * TILE + w;

            float a0 = 0.f, ax = 0.f, ay = 0.f, az = 0.f;
            float p00 = 0.f, dot = 0.f;
            float qx = 0.f, qy = 0.f, qz = 0.f;   // p01 = s0*f1
            float rx = 0.f, ry = 0.f, rz = 0.f;   // p10 = f0*s1

            int d = 0;
            if (n < N) d = g_deg[n];
            const int dc = min(d, CAP);
            if (n < N && lane == 0) g_deg[n] = 0;   // maintain zero-invariant

            int    my_s  = 0;
            float4 my_sh = make_float4(0.f, 0.f, 0.f, 0.f);
            if (lane < dc) {
                int2 se = g_bucket[n * CAP + lane];
                my_s    = se.x;
                my_sh   = *reinterpret_cast<const float4*>(sh + (size_t)se.y * 4);
            }

            for (int j = 0; j < dc; j++) {
                int   s   = __shfl_sync(0xffffffffu, my_s,    j);
                float s0  = __shfl_sync(0xffffffffu, my_sh.x, j);
                float s1x = __shfl_sync(0xffffffffu, my_sh.y, j);
                float s1y = __shfl_sync(0xffffffffu, my_sh.z, j);
                float s1z = __shfl_sync(0xffffffffu, my_sh.w, j);

                float4 v = __ldg(&g_nfT[s * 32 + lane]);  // one coalesced LDG.128
                float f0 = v.x, g0 = v.y, g1 = v.z, g2 = v.w;

                a0 += f0; ax += g0; ay += g1; az += g2;
                p00 = fmaf(s0, f0, p00);
                dot = fmaf(s1x, g0, fmaf(s1y, g1, fmaf(s1z, g2, dot)));
                qx  = fmaf(s0, g0, qx);
                qy  = fmaf(s0, g1, qy);
                qz  = fmaf(s0, g2, qz);
                rx  = fmaf(f0, s1x, rx);
                ry  = fmaf(f0, s1y, ry);
                rz  = fmaf(f0, s1z, rz);
            }

            const float scale = 1.0f / (1.5f * (float)max(d, 1));
            float* F = sF + w * FS;
            F[        lane] = a0 * scale;
            F[ 32   + lane] = ax * scale;
            F[ 64   + lane] = ay * scale;
            F[ 96   + lane] = az * scale;
            F[128   + lane] = p00 * scale;
            F[160   + lane] = dot * scale * INV_SQRT3;
            F[192   + lane] = qx * scale;   // c=0: p01
            F[224   + lane] = rx * scale;   // c=0: p10
            F[256   + lane] = qy * scale;   // c=1
            F[288   + lane] = ry * scale;
            F[320   + lane] = qz * scale;   // c=2
            F[352   + lane] = rz * scale;
        }
        __syncthreads();

        // ---------------- Phase B: 32 rows (8 nodes x 4) / 8 warps ---------
        const float4* Wq;
        int nodeBase, cc;
        if (w < 2) { Wq = sW0q; nodeBase = w * 4; cc = -1; }
        else       { cc = (w - 2) >> 1; nodeBase = ((w - 2) & 1) * 4; Wq = sW1q; }

        const float* pA = (cc < 0) ? (sF + nodeBase * FS)
                                   : (sF + nodeBase * FS + 32 + 32 * cc);
        const float* pB = (cc < 0) ? (sF + nodeBase * FS + 128)
                                   : (sF + nodeBase * FS + 192 + 64 * cc);

        float acc[4];
        #pragma unroll
        for (int r = 0; r < 4; r++) acc[r] = 0.f;

        #pragma unroll
        for (int q = 0; q < 8; q++) {            // u in [0,32)
            float4 wv = Wq[q * 32 + lane];
            #pragma unroll
            for (int r = 0; r < 4; r++) {
                float4 a = *reinterpret_cast<const float4*>(pA + r * FS + 4 * q);
                acc[r] = fmaf(a.x, wv.x, fmaf(a.y, wv.y,
                         fmaf(a.z, wv.z, fmaf(a.w, wv.w, acc[r]))));
            }
        }
        #pragma unroll
        for (int q = 0; q < 16; q++) {           // u in [32,96)
            float4 wv = Wq[(8 + q) * 32 + lane];
            #pragma unroll
            for (int r = 0; r < 4; r++) {
                float4 a = *reinterpret_cast<const float4*>(pB + r * FS + 4 * q);
                acc[r] = fmaf(a.x, wv.x, fmaf(a.y, wv.y,
                         fmaf(a.z, wv.z, fmaf(a.w, wv.w, acc[r]))));
            }
        }

        #pragma unroll
        for (int r = 0; r < 4; r++) {
            int n = tile * TILE + nodeBase + r;
            if (n < N) {
                if (cc < 0) out[(size_t)n * 128 + lane] = acc[r];
                else        out[(size_t)n * 128 + 32 + 3 * lane + cc] = acc[r];
            }
        }
    }
}

// ---------------------------------------------------------------------------
extern "C" void kernel_launch(void* const* d_in, const int* in_sizes, int n_in,
                              void* d_out, int out_size)
{
    const float* nf       = (const float*)d_in[0];
    const float* sh       = (const float*)d_in[1];
    const int*   senders  = (const int*)  d_in[2];
    const int*   recv     = (const int*)  d_in[3];
    const float* W0       = (const float*)d_in[4];
    const float* W1       = (const float*)d_in[5];
    const float* Ws0      = (const float*)d_in[6];
    const float* Ws1      = (const float*)d_in[7];
    float* out = (float*)d_out;

    int N = in_sizes[0] / 128;
    int E = in_sizes[2];

    int EB = (E + 511) / 512;          // edge blocks
    int TB = (N + 15) / 16;            // transpose blocks (16 nodes each)
    k_fill<<<EB + TB, 512>>>(recv, senders, nf, E, EB, N);
    k_main<<<NBLK, 256>>>(sh, W0, W1, Ws0, Ws1, out, N);
}